// round 6
// baseline (speedup 1.0000x reference)
#include <cuda_runtime.h>

#define BB 8
#define NQV 4096
#define NKV 4096
#define CC 256
#define KNN 16
#define HH 32
#define EPSV 1e-5f
#define GR 20
#define NCELL (GR * GR * GR)
#define GMIN (-4.5f)
#define GW 0.45f
#define FINF 3.402823466e38f
#define FULLM 0xFFFFFFFFu

// Scratch (device globals: allocation-free rule)
__device__ float    g_kvproj[BB * NKV * HH];
__device__ float    g_qterm [BB * NQV * HH];
__device__ unsigned g_topk  [BB * NQV * KNN];
// KV grid
__device__ unsigned g_cnt   [BB * NCELL];
__device__ unsigned g_cstart[BB * (NCELL + 1)];
__device__ unsigned g_coff  [BB * NCELL];
__device__ unsigned short g_cellid[BB * NKV];
__device__ float4   g_spts  [BB * NKV];   // reordered {x,y,z,|k|^2}
__device__ unsigned g_sidx  [BB * NKV];   // original kv index
// Query sort (for block-level locality)
__device__ unsigned g_qcnt  [BB * NCELL];
__device__ unsigned g_qoff  [BB * NCELL];
__device__ unsigned short g_qcellid[BB * NQV];
__device__ float4   g_qpts  [BB * NQV];   // sorted {x,y,z,|q|^2}
__device__ unsigned g_qidx  [BB * NQV];   // original query index (within batch)

__device__ __forceinline__ int cell_of(float x) {
    int c = (int)floorf((x - GMIN) * (1.0f / GW));
    return min(GR - 1, max(0, c));
}

// ---------------------------------------------------------------------------
// Grid build (fused kv+query passes)
// ---------------------------------------------------------------------------
__global__ void zero_kernel() {
    const int i = blockIdx.x * 256 + threadIdx.x;
    if (i < BB * NCELL) { g_cnt[i] = 0; g_qcnt[i] = 0; }
}

__global__ void bin_kernel(const float* __restrict__ kxyz,
                           const float* __restrict__ qxyz) {
    const int gi  = blockIdx.x * 512 + threadIdx.x;   // 128 x 512 = 65536
    const int isq = gi >> 15;
    const int i   = gi & 32767;
    const int b   = i >> 12;
    const float* xyz = isq ? qxyz : kxyz;
    const float x = xyz[(size_t)i * 3 + 0];
    const float y = xyz[(size_t)i * 3 + 1];
    const float z = xyz[(size_t)i * 3 + 2];
    const int cid = (cell_of(z) * GR + cell_of(y)) * GR + cell_of(x);
    if (isq) {
        g_qcellid[i] = (unsigned short)cid;
        atomicAdd(&g_qcnt[b * NCELL + cid], 1u);
    } else {
        g_cellid[i] = (unsigned short)cid;
        atomicAdd(&g_cnt[b * NCELL + cid], 1u);
    }
}

// 16 blocks: blockIdx.x = b*2 + isq. Warp-scan based, 2 barriers.
__global__ __launch_bounds__(1024) void scan_kernel() {
    __shared__ unsigned wsum[32];
    const int isq = blockIdx.x & 1;
    const int b   = blockIdx.x >> 1;
    const int tid = threadIdx.x, lane = tid & 31, warp = tid >> 5;
    const unsigned* cnt = (isq ? g_qcnt : g_cnt) + b * NCELL;
    const int base = tid * 8;
    unsigned loc[8], sum = 0;
#pragma unroll
    for (int j = 0; j < 8; ++j) {
        const unsigned v = (base + j < NCELL) ? cnt[base + j] : 0u;
        loc[j] = sum;
        sum += v;
    }
    unsigned incl = sum;
#pragma unroll
    for (int off = 1; off < 32; off <<= 1) {
        const unsigned v = __shfl_up_sync(FULLM, incl, off);
        if (lane >= off) incl += v;
    }
    if (lane == 31) wsum[warp] = incl;
    __syncthreads();
    if (warp == 0) {
        unsigned w = wsum[lane];
        unsigned wi = w;
#pragma unroll
        for (int off = 1; off < 32; off <<= 1) {
            const unsigned v = __shfl_up_sync(FULLM, wi, off);
            if (lane >= off) wi += v;
        }
        wsum[lane] = wi - w;   // exclusive
    }
    __syncthreads();
    const unsigned tpre = wsum[warp] + (incl - sum);  // exclusive prefix of thread
    if (isq) {
#pragma unroll
        for (int j = 0; j < 8; ++j)
            if (base + j < NCELL) g_qoff[b * NCELL + base + j] = tpre + loc[j];
    } else {
        unsigned* cst = g_cstart + (size_t)b * (NCELL + 1);
#pragma unroll
        for (int j = 0; j < 8; ++j)
            if (base + j < NCELL) {
                const unsigned v = tpre + loc[j];
                cst[base + j] = v;
                g_coff[b * NCELL + base + j] = v;
            }
        if (tid == 1023) cst[NCELL] = NKV;
    }
}

__global__ void scatter_kernel(const float* __restrict__ kxyz,
                               const float* __restrict__ qxyz) {
    const int gi  = blockIdx.x * 512 + threadIdx.x;
    const int isq = gi >> 15;
    const int i   = gi & 32767;
    const int b   = i >> 12;
    const int k   = i & (NKV - 1);
    const float* xyz = isq ? qxyz : kxyz;
    const float x = xyz[(size_t)i * 3 + 0];
    const float y = xyz[(size_t)i * 3 + 1];
    const float z = xyz[(size_t)i * 3 + 2];
    const float n2 = x * x + y * y + z * z;
    if (isq) {
        const int cid = g_qcellid[i];
        const unsigned pos = atomicAdd(&g_qoff[b * NCELL + cid], 1u);
        g_qpts[(size_t)b * NQV + pos] = make_float4(x, y, z, n2);
        g_qidx[(size_t)b * NQV + pos] = (unsigned)k;
    } else {
        const int cid = g_cellid[i];
        const unsigned pos = atomicAdd(&g_coff[b * NCELL + cid], 1u);
        g_spts[(size_t)b * NKV + pos] = make_float4(x, y, z, n2);
        g_sidx[(size_t)b * NKV + pos] = (unsigned)k;
    }
}

// ---------------------------------------------------------------------------
// Kernel: exact 16-NN, WARP-PER-QUERY grid traversal.
// Ring/cell loops are warp-uniform; lanes split each cell's candidate list
// (coalesced float4 loads). Per-lane sorted top-16; warp count gives exact
// conservative stopping; final 16x warp-argmin merge (set semantics).
// ---------------------------------------------------------------------------
__global__ __launch_bounds__(256) void knn_kernel()
{
    const int gw   = blockIdx.x * 8 + (threadIdx.x >> 5);  // query slot
    const int lane = threadIdx.x & 31;
    const int b    = gw >> 12;

    const float4 qp = g_qpts[gw];
    const float qx = qp.x, qy = qp.y, qz = qp.z, qn = qp.w;
    const float ax = -2.0f * qx, ay = -2.0f * qy, az = -2.0f * qz;

    const int cx = cell_of(qx), cy = cell_of(qy), cz = cell_of(qz);
    const float fx = qx - (GMIN + cx * GW);
    const float fy = qy - (GMIN + cy * GW);
    const float fz = qz - (GMIN + cz * GW);
    const float maxf = fmaxf(fmaxf(fmaxf(fx, GW - fx), fmaxf(fy, GW - fy)),
                             fmaxf(fz, GW - fz));

    float    s [16];
    unsigned si[16];
#pragma unroll
    for (int j = 0; j < 16; ++j) { s[j] = FINF; si[j] = 0u; }

    const float4*   sp  = g_spts + (size_t)b * NKV;
    const unsigned* sx  = g_sidx + (size_t)b * NKV;
    const unsigned* cst = g_cstart + (size_t)b * (NCELL + 1);

    for (int D = 0; D < GR; ++D) {
        if (D >= 1) {
            // stop if >=16 already-found candidates are strictly inside ring D
            const float rb = (float)D * GW - maxf;
            if (rb > 0.0f) {
                const float rb2 = rb * rb;
                int c = 0;
#pragma unroll
                for (int k = 0; k < 16; ++k) c += (s[k] + qn < rb2) ? 1 : 0;
#pragma unroll
                for (int off = 16; off > 0; off >>= 1)
                    c += __shfl_xor_sync(FULLM, c, off);
                if (c >= 16) break;
            }
        }
        for (int dz = -D; dz <= D; ++dz) {
            const int z = cz + dz;
            if (z < 0 || z >= GR) continue;
            const int adz = (dz < 0) ? -dz : dz;
            for (int dy = -D; dy <= D; ++dy) {
                const int y = cy + dy;
                if (y < 0 || y >= GR) continue;
                const int ady = (dy < 0) ? -dy : dy;
                const int step = (adz == D || ady == D) ? 1 : (2 * D > 0 ? 2 * D : 1);
                for (int dx = -D; dx <= D; dx += step) {
                    const int x = cx + dx;
                    if (x < 0 || x >= GR) continue;
                    const int cell = (z * GR + y) * GR + x;
                    const int p0 = cst[cell], p1 = cst[cell + 1];
                    if (p0 == p1) continue;
                    if (D >= 2) {
                        // exact cell min-dist^2 prune via warp count
                        const float clx = GMIN + x * GW;
                        const float cly = GMIN + y * GW;
                        const float clz = GMIN + z * GW;
                        const float bx = fmaxf(0.0f, fmaxf(clx - qx, qx - (clx + GW)));
                        const float by = fmaxf(0.0f, fmaxf(cly - qy, qy - (cly + GW)));
                        const float bz = fmaxf(0.0f, fmaxf(clz - qz, qz - (clz + GW)));
                        const float cmin2 = bx * bx + by * by + bz * bz;
                        int c = 0;
#pragma unroll
                        for (int k = 0; k < 16; ++k) c += (s[k] + qn < cmin2) ? 1 : 0;
#pragma unroll
                        for (int off = 16; off > 0; off >>= 1)
                            c += __shfl_xor_sync(FULLM, c, off);
                        if (c >= 16) continue;
                    }
                    for (int j = p0 + lane; j < p1; j += 32) {
                        const float4 p = sp[j];
                        float dd = fmaf(ax, p.x, p.w);
                        dd = fmaf(ay, p.y, dd);
                        dd = fmaf(az, p.z, dd);
                        if (dd < s[15]) {
                            unsigned ii = sx[j];
#pragma unroll
                            for (int k = 0; k < 16; ++k) {
                                const bool sw = dd < s[k];
                                const float    tf = s[k];
                                const unsigned ti = si[k];
                                if (sw) { s[k] = dd; si[k] = ii; dd = tf; ii = ti; }
                            }
                        }
                    }
                }
            }
        }
    }

    // Merge: 16 rounds of warp-argmin with pop-by-shift (unordered output set)
    unsigned myout = 0;
#pragma unroll 1
    for (int r = 0; r < 16; ++r) {
        float bv = s[0];
        int   bl = lane;
#pragma unroll
        for (int off = 16; off > 0; off >>= 1) {
            const float ov = __shfl_xor_sync(FULLM, bv, off);
            const int   ol = __shfl_xor_sync(FULLM, bl, off);
            if (ov < bv || (ov == bv && ol < bl)) { bv = ov; bl = ol; }
        }
        const unsigned wi = __shfl_sync(FULLM, si[0], bl);
        if (lane == r) myout = wi;
        if (lane == bl) {
#pragma unroll
            for (int k = 0; k < 15; ++k) { s[k] = s[k + 1]; si[k] = si[k + 1]; }
            s[15] = FINF;
        }
    }

    const int q = (b << 12) + (int)g_qidx[gw];
    if (lane < KNN) g_topk[(size_t)q * KNN + lane] = myout;
}

// ---------------------------------------------------------------------------
// Kernel A: projection GEMM (unchanged, known-good)
// ---------------------------------------------------------------------------
__global__ __launch_bounds__(256) void proj_kernel(
    const float* __restrict__ feat, const float* __restrict__ w1,
    const float* __restrict__ g1, const float* __restrict__ b1,
    const float* __restrict__ m1, const float* __restrict__ v1, int mode)
{
    __shared__ float AsubT[32][132];
    __shared__ float WT[32][36];

    const int tid  = threadIdx.x;
    const int row0 = blockIdx.x * 128;
    const int h0   = (tid & 7) * 4;
    const int m0   = (tid >> 3) * 4;

    float acc[4][4];
#pragma unroll
    for (int i = 0; i < 4; ++i)
#pragma unroll
        for (int j = 0; j < 4; ++j) acc[i][j] = 0.0f;

    for (int k0 = 0; k0 < CC; k0 += 32) {
        {
            const int q4 = (tid & 7) * 4;
            const int r  = tid >> 3;
#pragma unroll
            for (int j = 0; j < 4; ++j) {
                const int row = r + j * 32;
                const float4 v = *(const float4*)(feat + (size_t)(row0 + row) * CC + k0 + q4);
                AsubT[q4 + 0][row] = v.x;
                AsubT[q4 + 1][row] = v.y;
                AsubT[q4 + 2][row] = v.z;
                AsubT[q4 + 3][row] = v.w;
            }
        }
        {
            const int kk = tid & 31;
            const int hb = tid >> 5;
#pragma unroll
            for (int j = 0; j < 4; ++j) {
                const int hh = hb + j * 8;
                float w = w1[hh * (2 * CC) + k0 + kk];
                if (mode) w = w1[hh * (2 * CC) + CC + k0 + kk] - w;
                WT[kk][hh] = w;
            }
        }
        __syncthreads();
#pragma unroll
        for (int kk = 0; kk < 32; ++kk) {
            const float4 a = *(const float4*)&AsubT[kk][m0];
            const float4 w = *(const float4*)&WT[kk][h0];
            const float av[4] = {a.x, a.y, a.z, a.w};
            const float wv[4] = {w.x, w.y, w.z, w.w};
#pragma unroll
            for (int i = 0; i < 4; ++i)
#pragma unroll
                for (int j = 0; j < 4; ++j)
                    acc[i][j] = fmaf(av[i], wv[j], acc[i][j]);
        }
        __syncthreads();
    }

    float sv[4], tv[4];
#pragma unroll
    for (int j = 0; j < 4; ++j) {
        const int h = h0 + j;
        const float sc = g1[h] * rsqrtf(v1[h] + EPSV);
        sv[j] = sc;
        tv[j] = mode ? (b1[h] - m1[h] * sc) : 0.0f;
    }
    float* out = mode ? g_qterm : g_kvproj;
#pragma unroll
    for (int i = 0; i < 4; ++i) {
        float4 o;
        o.x = fmaf(acc[i][0], sv[0], tv[0]);
        o.y = fmaf(acc[i][1], sv[1], tv[1]);
        o.z = fmaf(acc[i][2], sv[2], tv[2]);
        o.w = fmaf(acc[i][3], sv[3], tv[3]);
        *(float4*)(out + (size_t)(row0 + m0 + i) * HH + h0) = o;
    }
}

// ---------------------------------------------------------------------------
// Kernel C: gather + add + leaky + max over K, then y = max @ w2^T + BN2 + leaky
// ---------------------------------------------------------------------------
__global__ __launch_bounds__(256) void fuse_kernel(
    const float* __restrict__ w2, const float* __restrict__ g2,
    const float* __restrict__ b2, const float* __restrict__ m2,
    const float* __restrict__ v2, float* __restrict__ out)
{
    __shared__ float w2t[HH][260];
    __shared__ float smaxT[HH][68];
    __shared__ float s2s[CC], t2s[CC];

    const int tid = threadIdx.x;

    for (int idx = tid; idx < CC * HH; idx += 256) {
        const int c = idx >> 5, h = idx & 31;
        w2t[h][c] = w2[idx];
    }
    {
        const float sc = g2[tid] * rsqrtf(v2[tid] + EPSV);
        s2s[tid] = sc;
        t2s[tid] = b2[tid] - m2[tid] * sc;
    }

    const int r0   = blockIdx.x * 64;
    const int b    = r0 >> 12;
    const int warp = tid >> 5, lane = tid & 31;
    const float* kvb = g_kvproj + (size_t)b * NKV * HH;

    for (int qi = warp * 8; qi < warp * 8 + 8; ++qi) {
        const int r = r0 + qi;
        const float qt = g_qterm[(size_t)r * HH + lane];
        const uint4* ip = (const uint4*)(g_topk + (size_t)r * KNN);
        const uint4 i0 = ip[0], i1 = ip[1], i2 = ip[2], i3 = ip[3];
        const unsigned id[16] = {i0.x, i0.y, i0.z, i0.w, i1.x, i1.y, i1.z, i1.w,
                                 i2.x, i2.y, i2.z, i2.w, i3.x, i3.y, i3.z, i3.w};
        float mx = -FINF;
#pragma unroll
        for (int k = 0; k < 16; ++k) {
            float v = kvb[(size_t)id[k] * HH + lane] + qt;
            v = fmaxf(v, 0.2f * v);
            mx = fmaxf(mx, v);
        }
        smaxT[lane][qi] = mx;
    }
    __syncthreads();

    const int q0 = (tid & 15) * 4;
    const int c0 = (tid >> 4) * 16;
    float acc[4][16];
#pragma unroll
    for (int i = 0; i < 4; ++i)
#pragma unroll
        for (int j = 0; j < 16; ++j) acc[i][j] = 0.0f;

#pragma unroll 8
    for (int kk = 0; kk < HH; ++kk) {
        const float4 a = *(const float4*)&smaxT[kk][q0];
        const float av[4] = {a.x, a.y, a.z, a.w};
        float bv[16];
#pragma unroll
        for (int j4 = 0; j4 < 4; ++j4) {
            const float4 t = *(const float4*)&w2t[kk][c0 + j4 * 4];
            bv[j4 * 4 + 0] = t.x; bv[j4 * 4 + 1] = t.y;
            bv[j4 * 4 + 2] = t.z; bv[j4 * 4 + 3] = t.w;
        }
#pragma unroll
        for (int i = 0; i < 4; ++i)
#pragma unroll
            for (int j = 0; j < 16; ++j)
                acc[i][j] = fmaf(av[i], bv[j], acc[i][j]);
    }

#pragma unroll
    for (int i = 0; i < 4; ++i) {
        const int r = r0 + q0 + i;
        float* op = out + (size_t)r * CC + c0;
#pragma unroll
        for (int j4 = 0; j4 < 4; ++j4) {
            float4 o;
            float y;
            y = fmaf(acc[i][j4 * 4 + 0], s2s[c0 + j4 * 4 + 0], t2s[c0 + j4 * 4 + 0]); o.x = fmaxf(y, 0.2f * y);
            y = fmaf(acc[i][j4 * 4 + 1], s2s[c0 + j4 * 4 + 1], t2s[c0 + j4 * 4 + 1]); o.y = fmaxf(y, 0.2f * y);
            y = fmaf(acc[i][j4 * 4 + 2], s2s[c0 + j4 * 4 + 2], t2s[c0 + j4 * 4 + 2]); o.z = fmaxf(y, 0.2f * y);
            y = fmaf(acc[i][j4 * 4 + 3], s2s[c0 + j4 * 4 + 3], t2s[c0 + j4 * 4 + 3]); o.w = fmaxf(y, 0.2f * y);
            *(float4*)(op + j4 * 4) = o;
        }
    }
}

// ---------------------------------------------------------------------------
extern "C" void kernel_launch(void* const* d_in, const int* in_sizes, int n_in,
                              void* d_out, int out_size)
{
    const float* qf   = (const float*)d_in[0];
    const float* qxyz = (const float*)d_in[1];
    const float* kvf  = (const float*)d_in[2];
    const float* kxyz = (const float*)d_in[3];
    const float* w1   = (const float*)d_in[4];
    const float* g1   = (const float*)d_in[5];
    const float* b1   = (const float*)d_in[6];
    const float* m1   = (const float*)d_in[7];
    const float* v1   = (const float*)d_in[8];
    const float* w2   = (const float*)d_in[9];
    const float* g2   = (const float*)d_in[10];
    const float* b2   = (const float*)d_in[11];
    const float* m2   = (const float*)d_in[12];
    const float* v2   = (const float*)d_in[13];
    float* out = (float*)d_out;

    zero_kernel<<<(BB * NCELL + 255) / 256, 256>>>();
    bin_kernel<<<128, 512>>>(kxyz, qxyz);
    scan_kernel<<<16, 1024>>>();
    scatter_kernel<<<128, 512>>>(kxyz, qxyz);
    knn_kernel<<<(BB * NQV) / 8, 256>>>();
    proj_kernel<<<256, 256>>>(kvf, w1, g1, b1, m1, v1, 0);
    proj_kernel<<<256, 256>>>(qf,  w1, g1, b1, m1, v1, 1);
    fuse_kernel<<<512, 256>>>(w2, g2, b2, m2, v2, out);
}

// round 7
// speedup vs baseline: 1.6624x; 1.6624x over previous
#include <cuda_runtime.h>

#define BB 8
#define NQV 4096
#define NKV 4096
#define CC 256
#define KNN 16
#define HH 32
#define EPSV 1e-5f
#define FINF 3.402823466e38f

// Scratch (device globals: allocation-free rule)
__device__ float    g_kvproj[BB * NKV * HH];   // s1 * (kv_feat @ w1a^T)
__device__ float    g_qterm [BB * NQV * HH];   // s1 * (q_feat @ (w1b-w1a)^T) + t1
__device__ unsigned g_topk  [BB * NQV * KNN];  // neighbor indices (unordered set)

// ---------------------------------------------------------------------------
// Kernel B: exact top-16 NN, 4-way candidate split per query.
// Block = 1024 threads = 256 queries x 4 splits (one block per SM -> 32 warps).
// Thread (q_local, split) scans candidates [split*1024, split*1024+1024) with a
// distance-only sorted chain. Partials merged in smem -> exact tau per query.
// Pass 2 recovers indices: d <= tau, slots via smem atomic (set semantics:
// downstream K-reduction is max, order irrelevant; ties capped at 16).
// ---------------------------------------------------------------------------
extern "C" __global__ __launch_bounds__(1024) void topk_kernel(
    const float* __restrict__ qxyz, const float* __restrict__ kxyz)
{
    extern __shared__ char smem_raw[];
    float4*   s_pts  = (float4*)smem_raw;                       // 64KB
    float*    s_part = (float*)(smem_raw + 65536);              // 64KB [k*1024+tid]
    unsigned* s_cnt  = (unsigned*)(smem_raw + 131072);          // 1KB
    float*    s_tau  = (float*)(smem_raw + 131072 + 1024);      // 1KB

    const int tid     = threadIdx.x;
    const int q_local = tid & 255;
    const int split   = tid >> 8;
    const int b       = blockIdx.x >> 4;               // 16 blocks per batch
    const int q       = b * NQV + (blockIdx.x & 15) * 256 + q_local;

    // Stage all 4096 points of this batch (original order -> j == kv index)
    const float* kb = kxyz + (size_t)b * NKV * 3;
    for (int i = tid; i < NKV; i += 1024) {
        const float x = kb[i * 3 + 0];
        const float y = kb[i * 3 + 1];
        const float z = kb[i * 3 + 2];
        s_pts[i] = make_float4(x, y, z, x * x + y * y + z * z);
    }
    if (tid < 256) s_cnt[tid] = 0;
    __syncthreads();

    const float qx = qxyz[(size_t)q * 3 + 0];
    const float qy = qxyz[(size_t)q * 3 + 1];
    const float qz = qxyz[(size_t)q * 3 + 2];
    const float ax = -2.0f * qx, ay = -2.0f * qy, az = -2.0f * qz;
    // ranking key d = |k|^2 - 2 q.k  (per-query constant |q|^2 dropped: exact)

    float s[16];
#pragma unroll
    for (int j = 0; j < 16; ++j) s[j] = FINF;

    // Pass 1: exact top-16 distances of this thread's quarter
    const int j0 = split * 1024;
    for (int t = j0; t < j0 + 1024; t += 4) {
        float d[4];
#pragma unroll
        for (int u = 0; u < 4; ++u) {
            const float4 p = s_pts[t + u];
            float dd = fmaf(ax, p.x, p.w);
            dd = fmaf(ay, p.y, dd);
            dd = fmaf(az, p.z, dd);
            d[u] = dd;
        }
#pragma unroll
        for (int u = 0; u < 4; ++u) {
            float dd = d[u];
            if (dd < s[15]) {
#pragma unroll
                for (int j = 0; j < 16; ++j) {
                    const float lo = fminf(dd, s[j]);
                    dd = fmaxf(dd, s[j]);
                    s[j] = lo;
                }
            }
        }
    }

    // Publish partials: layout [k][tid] -> conflict-free both directions
#pragma unroll
    for (int k = 0; k < 16; ++k) s_part[k * 1024 + tid] = s[k];
    __syncthreads();

    // Split-0 threads merge 4 partial lists -> exact global 16th (tau)
    if (split == 0) {
        float m[16];
#pragma unroll
        for (int k = 0; k < 16; ++k) m[k] = s[k];
#pragma unroll
        for (int sp = 1; sp < 4; ++sp) {
#pragma unroll
            for (int k = 0; k < 16; ++k) {
                float dd = s_part[k * 1024 + sp * 256 + q_local];
                if (dd < m[15]) {
#pragma unroll
                    for (int j = 0; j < 16; ++j) {
                        const float lo = fminf(dd, m[j]);
                        dd = fmaxf(dd, m[j]);
                        m[j] = lo;
                    }
                }
            }
        }
        s_tau[q_local] = m[15];
    }
    __syncthreads();

    // Pass 2: recover indices (d <= tau; #(d<tau)<=15, so >=16 qualify; cap 16)
    const float tau = s_tau[q_local];
    unsigned* o = g_topk + (size_t)q * KNN;
    for (int t = j0; t < j0 + 1024; ++t) {
        const float4 p = s_pts[t];
        float dd = fmaf(ax, p.x, p.w);
        dd = fmaf(ay, p.y, dd);
        dd = fmaf(az, p.z, dd);
        if (dd <= tau) {
            const unsigned slot = atomicAdd(&s_cnt[q_local], 1u);
            if (slot < KNN) o[slot] = (unsigned)t;
        }
    }
}

// ---------------------------------------------------------------------------
// Kernel A: projection GEMM (unchanged, known-good)
//   mode 0: W = w1[h][c]            -> g_kvproj, epilogue *= s1[h]
//   mode 1: W = w1[h][C+c]-w1[h][c] -> g_qterm,  epilogue = acc*s1[h] + t1[h]
// ---------------------------------------------------------------------------
__global__ __launch_bounds__(256) void proj_kernel(
    const float* __restrict__ feat, const float* __restrict__ w1,
    const float* __restrict__ g1, const float* __restrict__ b1,
    const float* __restrict__ m1, const float* __restrict__ v1, int mode)
{
    __shared__ float AsubT[32][132];
    __shared__ float WT[32][36];

    const int tid  = threadIdx.x;
    const int row0 = blockIdx.x * 128;
    const int h0   = (tid & 7) * 4;
    const int m0   = (tid >> 3) * 4;

    float acc[4][4];
#pragma unroll
    for (int i = 0; i < 4; ++i)
#pragma unroll
        for (int j = 0; j < 4; ++j) acc[i][j] = 0.0f;

    for (int k0 = 0; k0 < CC; k0 += 32) {
        {
            const int q4 = (tid & 7) * 4;
            const int r  = tid >> 3;
#pragma unroll
            for (int j = 0; j < 4; ++j) {
                const int row = r + j * 32;
                const float4 v = *(const float4*)(feat + (size_t)(row0 + row) * CC + k0 + q4);
                AsubT[q4 + 0][row] = v.x;
                AsubT[q4 + 1][row] = v.y;
                AsubT[q4 + 2][row] = v.z;
                AsubT[q4 + 3][row] = v.w;
            }
        }
        {
            const int kk = tid & 31;
            const int hb = tid >> 5;
#pragma unroll
            for (int j = 0; j < 4; ++j) {
                const int hh = hb + j * 8;
                float w = w1[hh * (2 * CC) + k0 + kk];
                if (mode) w = w1[hh * (2 * CC) + CC + k0 + kk] - w;
                WT[kk][hh] = w;
            }
        }
        __syncthreads();
#pragma unroll
        for (int kk = 0; kk < 32; ++kk) {
            const float4 a = *(const float4*)&AsubT[kk][m0];
            const float4 w = *(const float4*)&WT[kk][h0];
            const float av[4] = {a.x, a.y, a.z, a.w};
            const float wv[4] = {w.x, w.y, w.z, w.w};
#pragma unroll
            for (int i = 0; i < 4; ++i)
#pragma unroll
                for (int j = 0; j < 4; ++j)
                    acc[i][j] = fmaf(av[i], wv[j], acc[i][j]);
        }
        __syncthreads();
    }

    float sv[4], tv[4];
#pragma unroll
    for (int j = 0; j < 4; ++j) {
        const int h = h0 + j;
        const float sc = g1[h] * rsqrtf(v1[h] + EPSV);
        sv[j] = sc;
        tv[j] = mode ? (b1[h] - m1[h] * sc) : 0.0f;
    }
    float* out = mode ? g_qterm : g_kvproj;
#pragma unroll
    for (int i = 0; i < 4; ++i) {
        float4 o;
        o.x = fmaf(acc[i][0], sv[0], tv[0]);
        o.y = fmaf(acc[i][1], sv[1], tv[1]);
        o.z = fmaf(acc[i][2], sv[2], tv[2]);
        o.w = fmaf(acc[i][3], sv[3], tv[3]);
        *(float4*)(out + (size_t)(row0 + m0 + i) * HH + h0) = o;
    }
}

// ---------------------------------------------------------------------------
// Kernel C: gather + add + leaky + max over K, then y = max @ w2^T + BN2 + leaky
// Re-tiled: 512 threads/block, 64 queries, acc[4][8] (regs down, occupancy up).
// ---------------------------------------------------------------------------
__global__ __launch_bounds__(512) void fuse_kernel(
    const float* __restrict__ w2, const float* __restrict__ g2,
    const float* __restrict__ b2, const float* __restrict__ m2,
    const float* __restrict__ v2, float* __restrict__ out)
{
    __shared__ float w2t[HH][260];    // transposed w2, padded
    __shared__ float smaxT[HH][68];   // [h][q_local]
    __shared__ float s2s[CC], t2s[CC];

    const int tid = threadIdx.x;

    for (int idx = tid; idx < CC * HH; idx += 512) {
        const int c = idx >> 5, h = idx & 31;
        w2t[h][c] = w2[idx];
    }
    if (tid < 256) {
        const float sc = g2[tid] * rsqrtf(v2[tid] + EPSV);
        s2s[tid] = sc;
        t2s[tid] = b2[tid] - m2[tid] * sc;
    }

    const int r0   = blockIdx.x * 64;
    const int b    = r0 >> 12;
    const int warp = tid >> 5, lane = tid & 31;
    const float* kvb = g_kvproj + (size_t)b * NKV * HH;

    for (int qi = warp * 4; qi < warp * 4 + 4; ++qi) {
        const int r = r0 + qi;
        const float qt = g_qterm[(size_t)r * HH + lane];
        const uint4* ip = (const uint4*)(g_topk + (size_t)r * KNN);
        const uint4 i0 = ip[0], i1 = ip[1], i2 = ip[2], i3 = ip[3];
        const unsigned id[16] = {i0.x, i0.y, i0.z, i0.w, i1.x, i1.y, i1.z, i1.w,
                                 i2.x, i2.y, i2.z, i2.w, i3.x, i3.y, i3.z, i3.w};
        float mx = -FINF;
#pragma unroll
        for (int k = 0; k < 16; ++k) {
            float v = kvb[(size_t)id[k] * HH + lane] + qt;
            v = fmaxf(v, 0.2f * v);  // leaky relu (slope < 1)
            mx = fmaxf(mx, v);
        }
        smaxT[lane][qi] = mx;
    }
    __syncthreads();

    const int q0 = (tid & 15) * 4;
    const int c0 = (tid >> 4) * 8;
    float acc[4][8];
#pragma unroll
    for (int i = 0; i < 4; ++i)
#pragma unroll
        for (int j = 0; j < 8; ++j) acc[i][j] = 0.0f;

#pragma unroll 8
    for (int kk = 0; kk < HH; ++kk) {
        const float4 a = *(const float4*)&smaxT[kk][q0];
        const float av[4] = {a.x, a.y, a.z, a.w};
        float bv[8];
        {
            const float4 t0 = *(const float4*)&w2t[kk][c0];
            const float4 t1 = *(const float4*)&w2t[kk][c0 + 4];
            bv[0] = t0.x; bv[1] = t0.y; bv[2] = t0.z; bv[3] = t0.w;
            bv[4] = t1.x; bv[5] = t1.y; bv[6] = t1.z; bv[7] = t1.w;
        }
#pragma unroll
        for (int i = 0; i < 4; ++i)
#pragma unroll
            for (int j = 0; j < 8; ++j)
                acc[i][j] = fmaf(av[i], bv[j], acc[i][j]);
    }

#pragma unroll
    for (int i = 0; i < 4; ++i) {
        const int r = r0 + q0 + i;
        float* op = out + (size_t)r * CC + c0;
#pragma unroll
        for (int j4 = 0; j4 < 2; ++j4) {
            float4 o;
            float y;
            y = fmaf(acc[i][j4 * 4 + 0], s2s[c0 + j4 * 4 + 0], t2s[c0 + j4 * 4 + 0]); o.x = fmaxf(y, 0.2f * y);
            y = fmaf(acc[i][j4 * 4 + 1], s2s[c0 + j4 * 4 + 1], t2s[c0 + j4 * 4 + 1]); o.y = fmaxf(y, 0.2f * y);
            y = fmaf(acc[i][j4 * 4 + 2], s2s[c0 + j4 * 4 + 2], t2s[c0 + j4 * 4 + 2]); o.z = fmaxf(y, 0.2f * y);
            y = fmaf(acc[i][j4 * 4 + 3], s2s[c0 + j4 * 4 + 3], t2s[c0 + j4 * 4 + 3]); o.w = fmaxf(y, 0.2f * y);
            *(float4*)(op + j4 * 4) = o;
        }
    }
}

// ---------------------------------------------------------------------------
extern "C" void kernel_launch(void* const* d_in, const int* in_sizes, int n_in,
                              void* d_out, int out_size)
{
    const float* qf   = (const float*)d_in[0];   // (8,4096,256)
    const float* qxyz = (const float*)d_in[1];   // (8,4096,3)
    const float* kvf  = (const float*)d_in[2];   // (8,4096,256)
    const float* kxyz = (const float*)d_in[3];   // (8,4096,3)
    const float* w1   = (const float*)d_in[4];   // (32,512)
    const float* g1   = (const float*)d_in[5];
    const float* b1   = (const float*)d_in[6];
    const float* m1   = (const float*)d_in[7];
    const float* v1   = (const float*)d_in[8];
    const float* w2   = (const float*)d_in[9];   // (256,32)
    const float* g2   = (const float*)d_in[10];
    const float* b2   = (const float*)d_in[11];
    const float* m2   = (const float*)d_in[12];
    const float* v2   = (const float*)d_in[13];
    float* out = (float*)d_out;

    const int smem_topk = 65536 + 65536 + 1024 + 1024;   // 133KB
    cudaFuncSetAttribute(topk_kernel, cudaFuncAttributeMaxDynamicSharedMemorySize, smem_topk);

    topk_kernel<<<128, 1024, smem_topk>>>(qxyz, kxyz);
    proj_kernel<<<256, 256>>>(kvf, w1, g1, b1, m1, v1, 0);
    proj_kernel<<<256, 256>>>(qf,  w1, g1, b1, m1, v1, 1);
    fuse_kernel<<<512, 512>>>(w2, g2, b2, m2, v2, out);
}

// round 8
// speedup vs baseline: 2.0396x; 1.2269x over previous
#include <cuda_runtime.h>

#define BB 8
#define NQV 4096
#define NKV 4096
#define CC 256
#define KNN 16
#define HH 32
#define EPSV 1e-5f
#define FINF 3.402823466e38f
#define CAP 160

// Scratch (device globals: allocation-free rule)
__device__ float    g_kvproj[BB * NKV * HH];   // s1 * (kv_feat @ w1a^T)
__device__ float    g_qterm [BB * NQV * HH];   // s1 * (q_feat @ (w1b-w1a)^T) + t1
__device__ unsigned g_topk  [BB * NQV * KNN];  // neighbor indices (unordered set)

// ---------------------------------------------------------------------------
// Kernel B: exact top-16 NN. One thread per query, full 4096-candidate stream
// (minimum union-fire layout). Insert uses the PARALLEL sorted-insert form
//   s[j] = min(s[j], max(s[j-1], d))   (j = 15..0, s[-1] = -inf)
// -> dependency depth 2 instead of a 64-cycle serial chain.
// Indices are collected on the fire branch into a per-thread smem ring
// (superset of the final 16); emission filters against exact tau in scan
// order. Overflow (rare) falls back to an exact rescan.
// ---------------------------------------------------------------------------
extern "C" __global__ __launch_bounds__(256) void topk_kernel(
    const float* __restrict__ qxyz, const float* __restrict__ kxyz)
{
    extern __shared__ char smem_raw[];
    float4*         s_pts = (float4*)smem_raw;                   // 64KB
    unsigned short* s_buf = (unsigned short*)(smem_raw + 65536); // CAP*256*2 = 80KB

    const int tid = threadIdx.x;
    const int b   = blockIdx.x >> 4;               // 16 blocks per batch
    const int q   = b * NQV + (blockIdx.x & 15) * 256 + tid;

    // Stage all 4096 points of this batch (original order -> j == kv index)
    const float* kb = kxyz + (size_t)b * NKV * 3;
    for (int i = tid; i < NKV; i += 256) {
        const float x = kb[i * 3 + 0];
        const float y = kb[i * 3 + 1];
        const float z = kb[i * 3 + 2];
        s_pts[i] = make_float4(x, y, z, x * x + y * y + z * z);
    }
    __syncthreads();

    const float qx = qxyz[(size_t)q * 3 + 0];
    const float qy = qxyz[(size_t)q * 3 + 1];
    const float qz = qxyz[(size_t)q * 3 + 2];
    const float ax = -2.0f * qx, ay = -2.0f * qy, az = -2.0f * qz;
    // ranking key d = |k|^2 - 2 q.k  (per-query constant |q|^2 dropped: exact)

    float s[16];
#pragma unroll
    for (int j = 0; j < 16; ++j) s[j] = FINF;
    int cnt = 0;

    for (int t = 0; t < NKV; t += 8) {
        float d[8];
#pragma unroll
        for (int u = 0; u < 8; ++u) {
            const float4 p = s_pts[t + u];
            float dd = fmaf(ax, p.x, p.w);
            dd = fmaf(ay, p.y, dd);
            dd = fmaf(az, p.z, dd);
            d[u] = dd;
        }
#pragma unroll
        for (int u = 0; u < 8; ++u) {
            const float dd = d[u];
            if (dd < s[15]) {
                // parallel sorted insert (descending j reads old s[j-1])
#pragma unroll
                for (int j = 15; j >= 1; --j)
                    s[j] = fminf(s[j], fmaxf(s[j - 1], dd));
                s[0] = fminf(s[0], dd);
                if (cnt < CAP) s_buf[cnt * 256 + tid] = (unsigned short)(t + u);
                ++cnt;
            }
        }
    }

    // Emission: exact tau filter over the collected superset, scan order.
    const float tau = s[15];
    unsigned* o = g_topk + (size_t)q * KNN;
    int out = 0;
    if (cnt <= CAP) {
        for (int i = 0; i < cnt && out < KNN; ++i) {
            const int idx = s_buf[i * 256 + tid];
            const float4 p = s_pts[idx];
            float dd = fmaf(ax, p.x, p.w);
            dd = fmaf(ay, p.y, dd);
            dd = fmaf(az, p.z, dd);
            if (dd <= tau) o[out++] = (unsigned)idx;
        }
    } else {
        // ultra-rare overflow: exact rescan
        for (int t = 0; t < NKV && out < KNN; ++t) {
            const float4 p = s_pts[t];
            float dd = fmaf(ax, p.x, p.w);
            dd = fmaf(ay, p.y, dd);
            dd = fmaf(az, p.z, dd);
            if (dd <= tau) o[out++] = (unsigned)t;
        }
    }
}

// ---------------------------------------------------------------------------
// Kernel A: projection GEMM (unchanged, known-good)
//   mode 0: W = w1[h][c]            -> g_kvproj, epilogue *= s1[h]
//   mode 1: W = w1[h][C+c]-w1[h][c] -> g_qterm,  epilogue = acc*s1[h] + t1[h]
// ---------------------------------------------------------------------------
__global__ __launch_bounds__(256) void proj_kernel(
    const float* __restrict__ feat, const float* __restrict__ w1,
    const float* __restrict__ g1, const float* __restrict__ b1,
    const float* __restrict__ m1, const float* __restrict__ v1, int mode)
{
    __shared__ float AsubT[32][132];
    __shared__ float WT[32][36];

    const int tid  = threadIdx.x;
    const int row0 = blockIdx.x * 128;
    const int h0   = (tid & 7) * 4;
    const int m0   = (tid >> 3) * 4;

    float acc[4][4];
#pragma unroll
    for (int i = 0; i < 4; ++i)
#pragma unroll
        for (int j = 0; j < 4; ++j) acc[i][j] = 0.0f;

    for (int k0 = 0; k0 < CC; k0 += 32) {
        {
            const int q4 = (tid & 7) * 4;
            const int r  = tid >> 3;
#pragma unroll
            for (int j = 0; j < 4; ++j) {
                const int row = r + j * 32;
                const float4 v = *(const float4*)(feat + (size_t)(row0 + row) * CC + k0 + q4);
                AsubT[q4 + 0][row] = v.x;
                AsubT[q4 + 1][row] = v.y;
                AsubT[q4 + 2][row] = v.z;
                AsubT[q4 + 3][row] = v.w;
            }
        }
        {
            const int kk = tid & 31;
            const int hb = tid >> 5;
#pragma unroll
            for (int j = 0; j < 4; ++j) {
                const int hh = hb + j * 8;
                float w = w1[hh * (2 * CC) + k0 + kk];
                if (mode) w = w1[hh * (2 * CC) + CC + k0 + kk] - w;
                WT[kk][hh] = w;
            }
        }
        __syncthreads();
#pragma unroll
        for (int kk = 0; kk < 32; ++kk) {
            const float4 a = *(const float4*)&AsubT[kk][m0];
            const float4 w = *(const float4*)&WT[kk][h0];
            const float av[4] = {a.x, a.y, a.z, a.w};
            const float wv[4] = {w.x, w.y, w.z, w.w};
#pragma unroll
            for (int i = 0; i < 4; ++i)
#pragma unroll
                for (int j = 0; j < 4; ++j)
                    acc[i][j] = fmaf(av[i], wv[j], acc[i][j]);
        }
        __syncthreads();
    }

    float sv[4], tv[4];
#pragma unroll
    for (int j = 0; j < 4; ++j) {
        const int h = h0 + j;
        const float sc = g1[h] * rsqrtf(v1[h] + EPSV);
        sv[j] = sc;
        tv[j] = mode ? (b1[h] - m1[h] * sc) : 0.0f;
    }
    float* out = mode ? g_qterm : g_kvproj;
#pragma unroll
    for (int i = 0; i < 4; ++i) {
        float4 o;
        o.x = fmaf(acc[i][0], sv[0], tv[0]);
        o.y = fmaf(acc[i][1], sv[1], tv[1]);
        o.z = fmaf(acc[i][2], sv[2], tv[2]);
        o.w = fmaf(acc[i][3], sv[3], tv[3]);
        *(float4*)(out + (size_t)(row0 + m0 + i) * HH + h0) = o;
    }
}

// ---------------------------------------------------------------------------
// Kernel C: gather + add + leaky + max over K, then y = max @ w2^T + BN2 + leaky
// 512 threads/block, 64 queries, acc[4][8].
// ---------------------------------------------------------------------------
__global__ __launch_bounds__(512) void fuse_kernel(
    const float* __restrict__ w2, const float* __restrict__ g2,
    const float* __restrict__ b2, const float* __restrict__ m2,
    const float* __restrict__ v2, float* __restrict__ out)
{
    __shared__ float w2t[HH][260];    // transposed w2, padded
    __shared__ float smaxT[HH][68];   // [h][q_local]
    __shared__ float s2s[CC], t2s[CC];

    const int tid = threadIdx.x;

    for (int idx = tid; idx < CC * HH; idx += 512) {
        const int c = idx >> 5, h = idx & 31;
        w2t[h][c] = w2[idx];
    }
    if (tid < 256) {
        const float sc = g2[tid] * rsqrtf(v2[tid] + EPSV);
        s2s[tid] = sc;
        t2s[tid] = b2[tid] - m2[tid] * sc;
    }

    const int r0   = blockIdx.x * 64;
    const int b    = r0 >> 12;
    const int warp = tid >> 5, lane = tid & 31;
    const float* kvb = g_kvproj + (size_t)b * NKV * HH;

    for (int qi = warp * 4; qi < warp * 4 + 4; ++qi) {
        const int r = r0 + qi;
        const float qt = g_qterm[(size_t)r * HH + lane];
        const uint4* ip = (const uint4*)(g_topk + (size_t)r * KNN);
        const uint4 i0 = ip[0], i1 = ip[1], i2 = ip[2], i3 = ip[3];
        const unsigned id[16] = {i0.x, i0.y, i0.z, i0.w, i1.x, i1.y, i1.z, i1.w,
                                 i2.x, i2.y, i2.z, i2.w, i3.x, i3.y, i3.z, i3.w};
        float mx = -FINF;
#pragma unroll
        for (int k = 0; k < 16; ++k) {
            float v = kvb[(size_t)id[k] * HH + lane] + qt;
            v = fmaxf(v, 0.2f * v);  // leaky relu (slope < 1)
            mx = fmaxf(mx, v);
        }
        smaxT[lane][qi] = mx;
    }
    __syncthreads();

    const int q0 = (tid & 15) * 4;
    const int c0 = (tid >> 4) * 8;
    float acc[4][8];
#pragma unroll
    for (int i = 0; i < 4; ++i)
#pragma unroll
        for (int j = 0; j < 8; ++j) acc[i][j] = 0.0f;

#pragma unroll 8
    for (int kk = 0; kk < HH; ++kk) {
        const float4 a = *(const float4*)&smaxT[kk][q0];
        const float av[4] = {a.x, a.y, a.z, a.w};
        float bv[8];
        {
            const float4 t0 = *(const float4*)&w2t[kk][c0];
            const float4 t1 = *(const float4*)&w2t[kk][c0 + 4];
            bv[0] = t0.x; bv[1] = t0.y; bv[2] = t0.z; bv[3] = t0.w;
            bv[4] = t1.x; bv[5] = t1.y; bv[6] = t1.z; bv[7] = t1.w;
        }
#pragma unroll
        for (int i = 0; i < 4; ++i)
#pragma unroll
            for (int j = 0; j < 8; ++j)
                acc[i][j] = fmaf(av[i], bv[j], acc[i][j]);
    }

#pragma unroll
    for (int i = 0; i < 4; ++i) {
        const int r = r0 + q0 + i;
        float* op = out + (size_t)r * CC + c0;
#pragma unroll
        for (int j4 = 0; j4 < 2; ++j4) {
            float4 o;
            float y;
            y = fmaf(acc[i][j4 * 4 + 0], s2s[c0 + j4 * 4 + 0], t2s[c0 + j4 * 4 + 0]); o.x = fmaxf(y, 0.2f * y);
            y = fmaf(acc[i][j4 * 4 + 1], s2s[c0 + j4 * 4 + 1], t2s[c0 + j4 * 4 + 1]); o.y = fmaxf(y, 0.2f * y);
            y = fmaf(acc[i][j4 * 4 + 2], s2s[c0 + j4 * 4 + 2], t2s[c0 + j4 * 4 + 2]); o.z = fmaxf(y, 0.2f * y);
            y = fmaf(acc[i][j4 * 4 + 3], s2s[c0 + j4 * 4 + 3], t2s[c0 + j4 * 4 + 3]); o.w = fmaxf(y, 0.2f * y);
            *(float4*)(op + j4 * 4) = o;
        }
    }
}

// ---------------------------------------------------------------------------
extern "C" void kernel_launch(void* const* d_in, const int* in_sizes, int n_in,
                              void* d_out, int out_size)
{
    const float* qf   = (const float*)d_in[0];   // (8,4096,256)
    const float* qxyz = (const float*)d_in[1];   // (8,4096,3)
    const float* kvf  = (const float*)d_in[2];   // (8,4096,256)
    const float* kxyz = (const float*)d_in[3];   // (8,4096,3)
    const float* w1   = (const float*)d_in[4];   // (32,512)
    const float* g1   = (const float*)d_in[5];
    const float* b1   = (const float*)d_in[6];
    const float* m1   = (const float*)d_in[7];
    const float* v1   = (const float*)d_in[8];
    const float* w2   = (const float*)d_in[9];   // (256,32)
    const float* g2   = (const float*)d_in[10];
    const float* b2   = (const float*)d_in[11];
    const float* m2   = (const float*)d_in[12];
    const float* v2   = (const float*)d_in[13];
    float* out = (float*)d_out;

    const int smem_topk = 65536 + CAP * 256 * 2;   // 64KB pts + 80KB idx ring
    cudaFuncSetAttribute(topk_kernel, cudaFuncAttributeMaxDynamicSharedMemorySize, smem_topk);

    topk_kernel<<<128, 256, smem_topk>>>(qxyz, kxyz);
    proj_kernel<<<256, 256>>>(kvf, w1, g1, b1, m1, v1, 0);
    proj_kernel<<<256, 256>>>(qf,  w1, g1, b1, m1, v1, 1);
    fuse_kernel<<<512, 512>>>(w2, g2, b2, m2, v2, out);
}